// round 7
// baseline (speedup 1.0000x reference)
#include <cuda_runtime.h>
#include <cstdint>

#define DIM 128
#define MAX_N 50000
#define MAX_E 800000
#define SCAN_TILE 256
#define MAX_TILES ((MAX_N + SCAN_TILE - 1) / SCAN_TILE)   // 196

// ---------------------------------------------------------------------------
// Scratch (static __device__ arrays; no allocation)
// ---------------------------------------------------------------------------
__device__ int  g_counts[MAX_N];
__device__ int  g_offsets[MAX_N + 1];
__device__ int  g_cursors[MAX_N];
__device__ int  g_partials[MAX_TILES];
__device__ int  g_partials_scanned[MAX_TILES];
__device__ int2 g_sorted[MAX_E];   // {src, eid} grouped by dst

// ---------------------------------------------------------------------------
// Cache-policy helpers
// ---------------------------------------------------------------------------
__device__ __forceinline__ float4 ld_evict_last(const float* p, unsigned long long pol) {
    float4 a;
    asm volatile("ld.global.nc.L2::cache_hint.v4.f32 {%0, %1, %2, %3}, [%4], %5;"
                 : "=f"(a.x), "=f"(a.y), "=f"(a.z), "=f"(a.w)
                 : "l"(p), "l"(pol));
    return a;
}
__device__ __forceinline__ float4 ld_stream(const float* p) {
    float4 b;
    asm volatile("ld.global.cs.v4.f32 {%0, %1, %2, %3}, [%4];"
                 : "=f"(b.x), "=f"(b.y), "=f"(b.z), "=f"(b.w) : "l"(p));
    return b;
}

// ---------------------------------------------------------------------------
// K0: zero counts
// ---------------------------------------------------------------------------
__global__ void zero_counts_kernel(int n) {
    int i = blockIdx.x * blockDim.x + threadIdx.x;
    if (i < n) g_counts[i] = 0;
}

// ---------------------------------------------------------------------------
// K1: histogram of dst (no-return reduction)
// ---------------------------------------------------------------------------
__global__ void hist_kernel(const int* __restrict__ edge_index, int E) {
    int e = blockIdx.x * blockDim.x + threadIdx.x;
    if (e >= E) return;
    int dst = edge_index[E + e];
    asm volatile("red.global.add.u32 [%0], %1;"
                 :: "l"((unsigned*)&g_counts[dst]), "r"(1) : "memory");
}

// ---------------------------------------------------------------------------
// K2: per-tile reduce (tile = 256 counts)
// ---------------------------------------------------------------------------
__global__ void scan_reduce_kernel(int n) {
    __shared__ int sh[SCAN_TILE];
    int i = blockIdx.x * SCAN_TILE + threadIdx.x;
    int v = (i < n) ? g_counts[i] : 0;
    sh[threadIdx.x] = v;
    __syncthreads();
    for (int d = 128; d > 0; d >>= 1) {
        if (threadIdx.x < d) sh[threadIdx.x] += sh[threadIdx.x + d];
        __syncthreads();
    }
    if (threadIdx.x == 0) g_partials[blockIdx.x] = sh[0];
}

// ---------------------------------------------------------------------------
// K3: exclusive scan of tile partials (single block; num_tiles <= 256)
// ---------------------------------------------------------------------------
__global__ void scan_partials_kernel(int num_tiles, int n, int E) {
    __shared__ int sh[SCAN_TILE];
    int tid = threadIdx.x;
    int v = (tid < num_tiles) ? g_partials[tid] : 0;
    sh[tid] = v;
    __syncthreads();
    // inclusive Hillis-Steele
    for (int d = 1; d < SCAN_TILE; d <<= 1) {
        int t = (tid >= d) ? sh[tid - d] : 0;
        __syncthreads();
        sh[tid] += t;
        __syncthreads();
    }
    if (tid < num_tiles) g_partials_scanned[tid] = sh[tid] - v;  // exclusive
    if (tid == 0) g_offsets[n] = E;
}

// ---------------------------------------------------------------------------
// K4: per-tile exclusive scan + base, write offsets and cursors
// ---------------------------------------------------------------------------
__global__ void scan_tiles_kernel(int n) {
    __shared__ int sh[SCAN_TILE];
    int i = blockIdx.x * SCAN_TILE + threadIdx.x;
    int tid = threadIdx.x;
    int v = (i < n) ? g_counts[i] : 0;
    sh[tid] = v;
    __syncthreads();
    for (int d = 1; d < SCAN_TILE; d <<= 1) {
        int t = (tid >= d) ? sh[tid - d] : 0;
        __syncthreads();
        sh[tid] += t;
        __syncthreads();
    }
    if (i < n) {
        int off = sh[tid] - v + g_partials_scanned[blockIdx.x];
        g_offsets[i] = off;
        g_cursors[i] = off;
    }
}

// ---------------------------------------------------------------------------
// K5: scatter {src, eid} into dst-grouped order
// ---------------------------------------------------------------------------
__global__ void scatter_kernel(const int* __restrict__ edge_index, int E) {
    int e = blockIdx.x * blockDim.x + threadIdx.x;
    if (e >= E) return;
    int src = edge_index[e];
    int dst = edge_index[E + e];
    int pos = atomicAdd(&g_cursors[dst], 1);
    g_sorted[pos] = make_int2(src, e);
}

// ---------------------------------------------------------------------------
// K6: aggregate. One warp per node; lane l owns float4 chunk l.
// Batch-loads up to 32 {src,eid} pairs coalesced, broadcasts via shfl.
// No float atomics anywhere -> RED LTS traffic eliminated.
// ---------------------------------------------------------------------------
__global__ __launch_bounds__(256, 8)
void aggregate_kernel(const float* __restrict__ node_feat,
                      const float* __restrict__ edge_feat,
                      const float* __restrict__ eps,
                      float* __restrict__ out,
                      int N) {
    int warp = (blockIdx.x * blockDim.x + threadIdx.x) >> 5;
    int lane = threadIdx.x & 31;
    if (warp >= N) return;
    int node = warp;

    unsigned long long pol;
    asm volatile("createpolicy.fractional.L2::evict_last.b64 %0, 1.0;"
                 : "=l"(pol));

    int beg = g_offsets[node];
    int end = g_offsets[node + 1];

    // self term early
    float4 self = ld_evict_last(node_feat + (long long)node * DIM + lane * 4, pol);
    float s = 1.0f + eps[0];

    float4 acc = make_float4(0.f, 0.f, 0.f, 0.f);

    for (int base = beg; base < end; base += 32) {
        int cnt = end - base; if (cnt > 32) cnt = 32;
        // coalesced batch index load: lane l grabs pair (base + l)
        int2 my = make_int2(0, 0);
        if (lane < cnt) my = g_sorted[base + lane];

        #pragma unroll 4
        for (int k = 0; k < cnt; k++) {
            int sidx = __shfl_sync(0xffffffffu, my.x, k);
            int eidx = __shfl_sync(0xffffffffu, my.y, k);
            float4 a = ld_evict_last(node_feat + (long long)sidx * DIM + lane * 4, pol);
            float4 b = ld_stream(edge_feat + (long long)eidx * DIM + lane * 4);
            acc.x += fmaxf(a.x + b.x, 0.f);
            acc.y += fmaxf(a.y + b.y, 0.f);
            acc.z += fmaxf(a.z + b.z, 0.f);
            acc.w += fmaxf(a.w + b.w, 0.f);
        }
    }

    float4 r;
    r.x = fmaf(s, self.x, acc.x);
    r.y = fmaf(s, self.y, acc.y);
    r.z = fmaf(s, self.z, acc.z);
    r.w = fmaf(s, self.w, acc.w);
    reinterpret_cast<float4*>(out + (long long)node * DIM)[lane] = r;
}

// ---------------------------------------------------------------------------
// Launch
// inputs (metadata order): node_feat (N*D f32), edge_index (2*E i32),
//                          edge_feat (E*D f32), eps (1 f32)
// output: (N, D) float32
// ---------------------------------------------------------------------------
extern "C" void kernel_launch(void* const* d_in, const int* in_sizes, int n_in,
                              void* d_out, int out_size) {
    const float* node_feat = (const float*)d_in[0];
    const int* edge_index = (const int*)d_in[1];
    const float* edge_feat = (const float*)d_in[2];
    const float* eps = (const float*)d_in[3];
    float* out = (float*)d_out;

    int N = in_sizes[0] / DIM;
    int E = in_sizes[1] / 2;
    int num_tiles = (N + SCAN_TILE - 1) / SCAN_TILE;

    zero_counts_kernel<<<(N + 255) / 256, 256>>>(N);
    hist_kernel<<<(E + 255) / 256, 256>>>(edge_index, E);
    scan_reduce_kernel<<<num_tiles, SCAN_TILE>>>(N);
    scan_partials_kernel<<<1, SCAN_TILE>>>(num_tiles, N, E);
    scan_tiles_kernel<<<num_tiles, SCAN_TILE>>>(N);
    scatter_kernel<<<(E + 255) / 256, 256>>>(edge_index, E);

    long long agg_threads = (long long)N * 32;
    int agg_blocks = (int)((agg_threads + 255) / 256);
    aggregate_kernel<<<agg_blocks, 256>>>(node_feat, edge_feat, eps, out, N);
}